// round 3
// baseline (speedup 1.0000x reference)
#include <cuda_runtime.h>
#include <cuda_bf16.h>
#include <cstdint>

// out[i, f] = W[f, idx[i]] + b[f]
//   idx: [1,048,576] int32 in [0,4096); W: [64,4096] fp32; b: [64] fp32
//   out: [1M, 64] fp32 (268 MB). R2 @ MLP=4: DRAM 60%, latency still exposed.
//   R3: MLP=8 per thread, 32-bit index math, streaming stores.

#define VOCAB 4096
#define F_DIM 64
#define NUM_IDX (32 * 16 * 2048)
#define TOTAL_F4 (NUM_IDX * 16u)            // 16,777,216 float4 stores (fits u32)
#define UNROLL 8
#define G (TOTAL_F4 / UNROLL)               // 2,097,152

// Transposed, bias-fused table: Wt[v][f] = W[f][v] + b[f]. 1 MB, L2-resident.
__device__ float4 g_Wt[VOCAB * (F_DIM / 4)];

// ---------------------------------------------------------------------------
// Prologue: tiled transpose with bias fusion. Coalesced both sides.
// ---------------------------------------------------------------------------
__global__ void build_table_kernel(const float* __restrict__ W,
                                   const float* __restrict__ b) {
    __shared__ float tile[32][33];
    int vbase = blockIdx.x * 32;
    int fbase = blockIdx.y * 32;

    #pragma unroll
    for (int r = 0; r < 4; r++) {
        int f = threadIdx.y + r * 8;
        int v = threadIdx.x;
        tile[f][v] = W[(fbase + f) * VOCAB + (vbase + v)];
    }
    __syncthreads();

    float* Wt = reinterpret_cast<float*>(g_Wt);
    #pragma unroll
    for (int r = 0; r < 4; r++) {
        int v = threadIdx.y + r * 8;
        int f = threadIdx.x;
        Wt[(unsigned)(vbase + v) * F_DIM + (fbase + f)] =
            tile[f][v] + b[fbase + f];
    }
}

// ---------------------------------------------------------------------------
// Gather: 16 threads per index, each moves one float4. Unrolled x8 across
// chunks of size G: all 8 idx loads then all 8 table loads issue as
// independent batches (MLP_eff ~ 8); stores stay 512B-coalesced per warp.
// ---------------------------------------------------------------------------
__global__ void __launch_bounds__(256) gather_kernel(
        const int* __restrict__ idx, float4* __restrict__ out) {
    unsigned t = blockIdx.x * blockDim.x + threadIdx.x;
    unsigned f4 = t & 15u;

    int v[UNROLL];
    #pragma unroll
    for (int u = 0; u < UNROLL; u++)
        v[u] = __ldg(&idx[(t + u * G) >> 4]);

    float4 r[UNROLL];
    #pragma unroll
    for (int u = 0; u < UNROLL; u++)
        r[u] = __ldg(&g_Wt[(unsigned)v[u] * 16u + f4]);

    #pragma unroll
    for (int u = 0; u < UNROLL; u++)
        __stcs(&out[t + u * G], r[u]);
}

extern "C" void kernel_launch(void* const* d_in, const int* in_sizes, int n_in,
                              void* d_out, int out_size) {
    const int* x = (const int*)d_in[0];
    const float* W = (const float*)d_in[1];
    const float* b = (const float*)d_in[2];
    float4* out = (float4*)d_out;

    {
        dim3 threads(32, 8);
        dim3 blocks(VOCAB / 32, F_DIM / 32);
        build_table_kernel<<<blocks, threads>>>(W, b);
    }
    {
        unsigned total_threads = G;            // 2,097,152
        int threads = 256;
        unsigned blocks = total_threads / threads;  // 8192
        gather_kernel<<<blocks, threads>>>(x, out);
    }
}